// round 7
// baseline (speedup 1.0000x reference)
#include <cuda_runtime.h>
#include <cuda_bf16.h>

// Problem constants (fixed shapes from reference)
#define Bn 512
#define Tn 512
#define Cn 128
#define Ln 32
#define BLANKC 127       // last class is blank
#define EPSF 1e-7f
#define NEG2 -1e30f      // log2-domain -inf surrogate
#define FULLM 0xffffffffu
#define PCH 8            // prefetch depth (timesteps)
#define WPB 4            // warps (batches) per block -> one warp per SMSP
#define LN2F 0.69314718055994530942f

// bare MUFU ops (no fixup multiplies)
__device__ __forceinline__ float ex2(float x) {
    float r; asm("ex2.approx.f32 %0, %1;" : "=f"(r) : "f"(x)); return r;
}
__device__ __forceinline__ float lg2(float x) {
    float r; asm("lg2.approx.f32 %0, %1;" : "=f"(r) : "f"(x)); return r;
}

// log2-domain logaddexp: max + log2(1 + 2^(-|a-b|)).
// NEG-safe: 2^(-1e30) -> 0; a==b -> +1 (exact).
__device__ __forceinline__ float lae2(float a, float b) {
    float m = fmaxf(a, b);
    float d = -fabsf(a - b);
    return m + lg2(1.0f + ex2(d));
}

// Warp-per-batch CTC forward, LOG2 domain.
// Lane i owns alpha[2i] (blank, aL) and alpha[2i+1] (label i, aH); lane 31
// also owns alpha[64] (aE; its update is lane-local -- no shfl needed).
// Per step: ONE shfl_up + three log2-sum-exp2 updates; no barriers, no
// fixup multiplies (ex2/lg2 used raw); single *ln2 at the very end.
__global__ __launch_bounds__(WPB * 32, 8)
void CTCLayer_kernel(const int* __restrict__ y_true,
                     const float* __restrict__ y_pred,
                     float* __restrict__ out) {
    const int lane = threadIdx.x & 31;
    const int b    = blockIdx.x * WPB + (threadIdx.x >> 5);
    const float* __restrict__ row0 = y_pred + (size_t)b * Tn * Cn;

    // Odd state 2i+1 skip: i>0 and label[i] != label[i-1] (labels never BLANK).
    const int lab     = y_true[b * Ln + lane];
    const int labPrev = __shfl_up_sync(FULLM, lab, 1);
    const bool skip   = (lane > 0 && lab != labPrev);

    // ---- prefetch chunk 0 --------------------------------------------------
    float curL[PCH], curB[PCH], nxtL[PCH], nxtB[PCH];
    #pragma unroll
    for (int j = 0; j < PCH; ++j) {
        curL[j] = __ldcs(row0 + j * Cn + lab);     // scattered, touched once
        curB[j] = __ldg (row0 + j * Cn + BLANKC);  // warp-broadcast sector
    }

    // t = 0 init (log2 domain): alpha[0]=lg2(pB), alpha[1]=lg2(pL) on lane 0.
    float aL = (lane == 0) ? lg2(curB[0] + EPSF) : NEG2;
    float aH = (lane == 0) ? lg2(curL[0] + EPSF) : NEG2;
    float aE = NEG2;

    #pragma unroll 1
    for (int c = 0; c < Tn / PCH; ++c) {
        if (c + 1 < Tn / PCH) {
            const float* rw = row0 + (size_t)(c + 1) * PCH * Cn;
            #pragma unroll
            for (int j = 0; j < PCH; ++j) {
                nxtL[j] = __ldcs(rw + j * Cn + lab);
                nxtB[j] = __ldg (rw + j * Cn + BLANKC);
            }
        }
        const int j0 = (c == 0) ? 1 : 0;   // chunk 0: t=0 consumed by init
        #pragma unroll
        for (int j = 0; j < PCH; ++j) {
            if (j < j0) continue;
            float lp2L = lg2(curL[j] + EPSF);      // off critical path
            float lp2B = lg2(curB[j] + EPSF);

            // Off-chain (independent of shfl): tail state 64 and nH's partial max
            float nE = lae2(aE, aH) + lp2B;        // lane 31's state (others junk, harmless)
            float m2 = fmaxf(aH, aL);

            float ph = __shfl_up_sync(FULLM, aH, 1);   // alpha[2i-1]
            if (lane == 0) ph = NEG2;

            // even state 2i: from {2i, 2i-1}
            float nL = lae2(aL, ph) + lp2B;
            // odd state 2i+1: from {2i+1, 2i, [2i-1]} -- 3-way with prehoisted m2
            float cc = skip ? ph : NEG2;
            float m3 = fmaxf(m2, cc);
            float s3 = ex2(aH - m3) + ex2(aL - m3) + ex2(cc - m3);
            float nH = m3 + lg2(s3) + lp2L;

            aL = nL; aH = nH; aE = nE;
        }
        #pragma unroll
        for (int j = 0; j < PCH; ++j) { curL[j] = nxtL[j]; curB[j] = nxtB[j]; }
    }

    // loss = -ln2 * log2addexp(alpha[64], alpha[63])
    if (lane == 31) {
        out[b] = -LN2F * lae2(aE, aH);
    }
}

extern "C" void kernel_launch(void* const* d_in, const int* in_sizes, int n_in,
                              void* d_out, int out_size) {
    // Resolve input order defensively by element count:
    // y_true: B*L = 16384 int32 ; y_pred: B*T*C = 33554432 float32
    int it = 0, ip = 1;
    if (n_in >= 2 && in_sizes[0] != Bn * Ln) { it = 1; ip = 0; }
    const int*   y_true = (const int*)d_in[it];
    const float* y_pred = (const float*)d_in[ip];
    float*       out    = (float*)d_out;
    (void)out_size;

    CTCLayer_kernel<<<Bn / WPB, WPB * 32>>>(y_true, y_pred, out);
}